// round 15
// baseline (speedup 1.0000x reference)
#include <cuda_runtime.h>
#include <cuda_fp16.h>
#include <math.h>

#define BB 16
#define CC 384
#define HH 96
#define WW 96
#define HW (HH*WW)
#define CAND 2048
#define ANCH 512
#define KK2 49
#define TAU_INV 10.0f

// ---------------- scratch (device globals; no allocation anywhere) ----------------
__device__ __half g_tn[(size_t)BB*HW*CC];     // teacher, normalized, channels-last, fp16
__device__ __half g_sn[(size_t)BB*HW*CC];     // student,  normalized, channels-last, fp16
__device__ float g_sims[(size_t)BB*CAND*KK2]; // teacher sims (already /TAU), by ORIGINAL id
__device__ float g_ent[BB*CAND];              // by ORIGINAL id
__device__ int   g_order[CAND];               // candidate ids, Morton-sorted
__device__ int   g_sel[BB*ANCH];              // selected ids, Morton-sorted per batch
__device__ float g_loss = 0.0f;
__device__ unsigned g_count = 0u;

// pixel offsets dy*WW+dx, row-major 7x7, padded to 52 with 0 (center: L1-resident)
__constant__ int c_doff[52] = {
 -291,-290,-289,-288,-287,-286,-285,
 -195,-194,-193,-192,-191,-190,-189,
  -99, -98, -97, -96, -95, -94, -93,
   -3,  -2,  -1,   0,   1,   2,   3,
   93,  94,  95,  96,  97,  98,  99,
  189, 190, 191, 192, 193, 194, 195,
  285, 286, 287, 288, 289, 290, 291,
    0,   0,   0 };

__device__ __forceinline__ unsigned morton7(int y, int x) {
    unsigned m = 0;
#pragma unroll
    for (int i = 0; i < 7; i++)
        m |= (((unsigned)(y >> i) & 1u) << (2 * i + 1)) | (((unsigned)(x >> i) & 1u) << (2 * i));
    return m;
}

// ---------------- candidate Morton sort body (256 threads, 4 pairs/round) ---------
__device__ void sort_candidates(const int* __restrict__ anchors,
                                unsigned* key, int* id) {
    int t = threadIdx.x;                 // 256
#pragma unroll
    for (int h = 0; h < 8; h++) {
        int m = t + h * 256;
        key[m] = morton7(anchors[2 * m], anchors[2 * m + 1]);
        id[m]  = m;
    }
    __syncthreads();
    for (int kk = 2; kk <= CAND; kk <<= 1) {
        for (int j = kk >> 1; j > 0; j >>= 1) {
            int ii[4], pp[4]; unsigned av[4], bv[4]; int ai[4], bi[4];
#pragma unroll
            for (int q = 0; q < 4; q++) {
                int tt = t + q * 256;
                ii[q] = ((tt & ~(j - 1)) << 1) | (tt & (j - 1));
                pp[q] = ii[q] | j;
                av[q] = key[ii[q]]; bv[q] = key[pp[q]];
                ai[q] = id[ii[q]];  bi[q] = id[pp[q]];
            }
#pragma unroll
            for (int q = 0; q < 4; q++) {
                bool up = ((ii[q] & kk) == 0);
                if ((av[q] > bv[q]) == up) {
                    key[ii[q]] = bv[q]; key[pp[q]] = av[q];
                    id[ii[q]]  = bi[q]; id[pp[q]]  = ai[q];
                }
            }
            __syncthreads();
        }
    }
#pragma unroll
    for (int h = 0; h < 8; h++) g_order[t + h * 256] = id[t + h * 256];
}

// ---------------- shared norm-transpose body (fp16 tile) --------------------------
#define PIX 32
#define TROW 42   // halves per tile row (84B stride: 4B-aligned, <=2-way LDS conflicts)
__device__ __forceinline__ void norm_body(const float* __restrict__ in, __half* gout,
                                          int blk, __half* tile,
                                          float (*ssum)[PIX + 1], float* rinv) {
    int b    = blk / (HW / PIX);
    int pix0 = (blk % (HW / PIX)) * PIX;
    int t    = threadIdx.x;
    int p4   = t & 7;                        // float4 pixel index (0..7)
    int cr   = t >> 3;                       // channel row group (0..31)
    const float* src = in + (size_t)b * CC * HW + pix0;
    float a0 = 0.f, a1 = 0.f, a2 = 0.f, a3 = 0.f;
#pragma unroll
    for (int i = 0; i < CC / 32; i++) {      // 12 iters, LDG.128, fully coalesced
        int c = i * 32 + cr;
        float4 v = *(const float4*)(src + (size_t)c * HW + p4 * 4);
        *(__half2*)&tile[c * TROW + p4 * 4]     = __floats2half2_rn(v.x, v.y);
        *(__half2*)&tile[c * TROW + p4 * 4 + 2] = __floats2half2_rn(v.z, v.w);
        a0 = fmaf(v.x, v.x, a0);
        a1 = fmaf(v.y, v.y, a1);
        a2 = fmaf(v.z, v.z, a2);
        a3 = fmaf(v.w, v.w, a3);
    }
    ssum[cr][p4 * 4 + 0] = a0;
    ssum[cr][p4 * 4 + 1] = a1;
    ssum[cr][p4 * 4 + 2] = a2;
    ssum[cr][p4 * 4 + 3] = a3;
    __syncthreads();
    if (t < PIX) {                           // one warp: reduce 32 partials/pixel
        float s = 0.0f;
#pragma unroll
        for (int r = 0; r < 32; r++) s += ssum[r][t];
        rinv[t] = 1.0f / fmaxf(sqrtf(s), 1e-12f);
    }
    __syncthreads();
    int lane = t & 31, w = t >> 5;           // 8 warps, 4 pixels each
    __half2* dst = (__half2*)(gout + ((size_t)b * HW + pix0) * CC);
#pragma unroll
    for (int j = 0; j < PIX / 8; j++) {      // 4 pixels per warp
        int pp = w * (PIX / 8) + j;
        float r = rinv[pp];
#pragma unroll
        for (int i2 = 0; i2 < CC / 64; i2++) {  // 6, 128B coalesced half2 stores
            int h2i = lane + 32 * i2;            // half2 index 0..191
            int c = 2 * h2i;
            float va = __half2float(tile[c * TROW + pp]);
            float vb = __half2float(tile[(c + 1) * TROW + pp]);
            dst[(size_t)pp * (CC / 2) + h2i] = __floats2half2_rn(va * r, vb * r);
        }
    }
}

// ---------------- k1a: teacher norm + sort block (stream 0) ----------------------
__global__ void __launch_bounds__(256) k_norm_t(const float* __restrict__ teacher,
                                                const int* __restrict__ anchors) {
    __shared__ __align__(16) __half tile[CC * TROW];   // 32256 B
    __shared__ float ssum[32][PIX + 1];
    __shared__ float rinv[PIX];
    const int bpt = BB * HW / PIX;                     // 4608
    int blk = blockIdx.x;
    if (blk >= bpt) {                                  // sort block
        unsigned* key = (unsigned*)tile;
        int* id = (int*)(key + CAND);
        sort_candidates(anchors, key, id);
        return;
    }
    norm_body(teacher, g_tn, blk, tile, ssum, rinv);
}

// ---------------- k1b: student norm (side stream, overlapped with k_cand) --------
__global__ void __launch_bounds__(256) k_norm_s(const float* __restrict__ student) {
    __shared__ __align__(16) __half tile[CC * TROW];
    __shared__ float ssum[32][PIX + 1];
    __shared__ float rinv[PIX];
    norm_body(student, g_sn, blockIdx.x, tile, ssum, rinv);
}

// ---------------- distributed window sims (fp16, fp32 accumulate) ----------------
template <int NB>
__device__ __forceinline__ void sims_batch(const uint4* __restrict__ cp, int ci,
                                           __half2 c0, __half2 c1, __half2 c2, __half2 c3,
                                           int obase, int g, float* s) {
    uint4 n[NB];
#pragma unroll
    for (int j = 0; j < NB; j++)
        n[j] = cp[ci + c_doff[g * 13 + obase + j] * (CC / 8)];
#pragma unroll
    for (int j = 0; j < NB; j++) {
        __half2 a = __hmul2(c0, *(__half2*)&n[j].x);
        a = __hfma2(c1, *(__half2*)&n[j].y, a);
        a = __hfma2(c2, *(__half2*)&n[j].z, a);
        a = __hfma2(c3, *(__half2*)&n[j].w, a);
        float2 f = __half22float2(a);
        s[obase + j] += f.x + f.y;
    }
}

__device__ __forceinline__ void window_sims13(const __half* __restrict__ feat,
                                              int b, int y, int x,
                                              int g, int l, float s[13]) {
    const uint4* cp = ((const uint4*)(feat + (size_t)b * HW * CC))
                    + (size_t)(y * WW + x) * (CC / 8);
#pragma unroll
    for (int j = 0; j < 13; j++) s[j] = 0.0f;
#pragma unroll
    for (int i = 0; i < 6; i++) {
        int ci = l + 8 * i;
        uint4 cv = cp[ci];
        __half2 c0 = *(__half2*)&cv.x, c1 = *(__half2*)&cv.y;
        __half2 c2 = *(__half2*)&cv.z, c3 = *(__half2*)&cv.w;
        sims_batch<5>(cp, ci, c0, c1, c2, c3, 0, g, s);
        sims_batch<4>(cp, ci, c0, c1, c2, c3, 5, g, s);
        sims_batch<4>(cp, ci, c0, c1, c2, c3, 9, g, s);
    }
#pragma unroll
    for (int j = 0; j < 13; j++) {
        float v = s[j];
        v += __shfl_xor_sync(0xffffffffu, v, 1);
        v += __shfl_xor_sync(0xffffffffu, v, 2);
        v += __shfl_xor_sync(0xffffffffu, v, 4);
        s[j] = v * TAU_INV;
    }
}

// ---------------- k2: candidate sims (stored) + entropy, Morton-ordered ----------
__global__ void __launch_bounds__(256, 4) k_cand(const int* __restrict__ anchors) {
    int gw   = (blockIdx.x * blockDim.x + threadIdx.x) >> 5;
    int lane = threadIdx.x & 31;
    if (gw >= BB * CAND) return;
    int b = gw >> 11;                  // / CAND
    int m = g_order[gw & (CAND - 1)];  // Morton-sorted processing order
    int y = anchors[2 * m], x = anchors[2 * m + 1];
    int g = lane >> 3, l = lane & 7;
    bool lead = (l == 0);

    float s[13];
    window_sims13(g_tn, b, y, x, g, l, s);

    float* srow = g_sims + ((size_t)(b << 11) + m) * KK2;
    if (lead) {
#pragma unroll
        for (int j = 0; j < 13; j++) {
            int o = g * 13 + j;
            if (o < KK2) srow[o] = s[j];
        }
    }

    float mx = -1e30f;
#pragma unroll
    for (int j = 0; j < 13; j++) {
        int o = g * 13 + j;
        if (o < KK2) mx = fmaxf(mx, s[j]);
    }
#pragma unroll
    for (int off = 16; off; off >>= 1) mx = fmaxf(mx, __shfl_xor_sync(0xffffffffu, mx, off));

    float S = 0.0f;
#pragma unroll
    for (int j = 0; j < 13; j++) {
        int o = g * 13 + j;
        if (lead && o < KK2) S += __expf(s[j] - mx);
    }
#pragma unroll
    for (int off = 16; off; off >>= 1) S += __shfl_xor_sync(0xffffffffu, S, off);
    float rS = 1.0f / S;

    float tacc = 0.0f;
#pragma unroll
    for (int j = 0; j < 13; j++) {
        int o = g * 13 + j;
        if (lead && o < KK2) {
            float p = __expf(s[j] - mx) * rS;
            tacc += p * __logf(p + 1e-6f);
        }
    }
#pragma unroll
    for (int off = 16; off; off >>= 1) tacc += __shfl_xor_sync(0xffffffffu, tacc, off);

    if (lane == 0) g_ent[(b << 11) | m] = -tacc;
}

// ---------------- k3: top-512 per batch (256 thr, 4 pairs/round) + Morton re-sort -
__global__ void __launch_bounds__(256) k_topk(const int* __restrict__ anchors) {
    __shared__ float v[CAND];
    __shared__ int   idx[CAND];
    __shared__ unsigned mk[ANCH];
    __shared__ int      mi[ANCH];
    int b = blockIdx.x;
    int t = threadIdx.x;   // 256
#pragma unroll
    for (int h = 0; h < 8; h++) {
        int m = t + h * 256;
        v[m]   = g_ent[b * CAND + m];
        idx[m] = m;
    }
    __syncthreads();
    for (int kk = 2; kk <= CAND; kk <<= 1) {
        for (int j = kk >> 1; j > 0; j >>= 1) {
            int ii[4], pp[4]; float av[4], bv[4]; int ai[4], bi[4];
#pragma unroll
            for (int q = 0; q < 4; q++) {
                int tt = t + q * 256;
                ii[q] = ((tt & ~(j - 1)) << 1) | (tt & (j - 1));
                pp[q] = ii[q] | j;
                av[q] = v[ii[q]]; bv[q] = v[pp[q]];
                ai[q] = idx[ii[q]]; bi[q] = idx[pp[q]];
            }
#pragma unroll
            for (int q = 0; q < 4; q++) {
                bool up = ((ii[q] & kk) == 0);
                if ((av[q] > bv[q]) == up) {
                    v[ii[q]] = bv[q]; v[pp[q]] = av[q];
                    idx[ii[q]] = bi[q]; idx[pp[q]] = ai[q];
                }
            }
            __syncthreads();
        }
    }
#pragma unroll
    for (int h = 0; h < 2; h++) {
        int m = t + h * 256;
        int id = idx[m];
        mi[m] = id;
        mk[m] = morton7(anchors[2 * id], anchors[2 * id + 1]);
    }
    __syncthreads();
    for (int kk = 2; kk <= ANCH; kk <<= 1) {
        for (int j = kk >> 1; j > 0; j >>= 1) {
            int i  = ((t & ~(j - 1)) << 1) | (t & (j - 1));
            int p2 = i | j;
            bool up = ((i & kk) == 0);
            unsigned ki = mk[i], kp = mk[p2];
            if ((ki > kp) == up) {
                mk[i] = kp; mk[p2] = ki;
                int ti = mi[i]; mi[i] = mi[p2]; mi[p2] = ti;
            }
            __syncthreads();
        }
    }
#pragma unroll
    for (int h = 0; h < 2; h++) {
        int m = t + h * 256;
        g_sel[b * ANCH + m] = mi[m];
    }
}

// ---------------- k4: KL divergence + fused finalize (completion counter) --------
// 64-thread blocks (2 warps = 2 anchors), grid 4096: finer scheduling granularity.
__global__ void __launch_bounds__(64, 16) k_kl(const int* __restrict__ anchors,
                                               float* __restrict__ out) {
    int tid  = threadIdx.x;
    int wid  = tid >> 5, lane = tid & 31;
    int gw   = blockIdx.x * 2 + wid;
    int b = gw >> 9;             // / ANCH
    int m = g_sel[gw];
    int y = anchors[2 * m], x = anchors[2 * m + 1];
    int g = lane >> 3, l = lane & 7;
    bool lead = (l == 0);

    float ss[13];
    window_sims13(g_sn, b, y, x, g, l, ss);

    const float* trow = g_sims + ((size_t)(b << 11) + m) * KK2;
    float st[13];
#pragma unroll
    for (int j = 0; j < 13; j++) {
        int o = g * 13 + j;
        st[j] = (o < KK2) ? trow[o] : -1e30f;   // group-broadcast loads
    }

    float mxs = -1e30f, mxt = -1e30f;
#pragma unroll
    for (int j = 0; j < 13; j++) {
        int o = g * 13 + j;
        if (o < KK2) mxs = fmaxf(mxs, ss[j]);
        mxt = fmaxf(mxt, st[j]);                // invalid slots are -1e30
    }
#pragma unroll
    for (int off = 16; off; off >>= 1) {
        mxs = fmaxf(mxs, __shfl_xor_sync(0xffffffffu, mxs, off));
        mxt = fmaxf(mxt, __shfl_xor_sync(0xffffffffu, mxt, off));
    }

    float Ss = 0.0f, St = 0.0f;
#pragma unroll
    for (int j = 0; j < 13; j++) {
        int o = g * 13 + j;
        if (lead && o < KK2) {
            Ss += __expf(ss[j] - mxs);
            St += __expf(st[j] - mxt);
        }
    }
#pragma unroll
    for (int off = 16; off; off >>= 1) {
        Ss += __shfl_xor_sync(0xffffffffu, Ss, off);
        St += __shfl_xor_sync(0xffffffffu, St, off);
    }
    float ls = __logf(Ss), lt = __logf(St);
    float rSt = 1.0f / St;

    float kacc = 0.0f;
#pragma unroll
    for (int j = 0; j < 13; j++) {
        int o = g * 13 + j;
        if (lead && o < KK2) {
            float dt = st[j] - mxt - lt;
            float ds = ss[j] - mxs - ls;
            kacc += __expf(st[j] - mxt) * (dt - ds);
        }
    }
#pragma unroll
    for (int off = 16; off; off >>= 1) kacc += __shfl_xor_sync(0xffffffffu, kacc, off);

    if (lane == 0) atomicAdd(&g_loss, kacc * rSt);

    // fused finalize: last block writes out and resets accumulators (replay-safe)
    __syncthreads();
    if (tid == 0) {
        __threadfence();
        unsigned old = atomicAdd(&g_count, 1u);
        if (old == (unsigned)(BB * ANCH / 2 - 1)) {
            float tot = atomicAdd(&g_loss, 0.0f);
            out[0] = tot / (float)(BB * ANCH);
            g_loss  = 0.0f;
            g_count = 0u;
        }
    }
}

// ---------------- launch: forked graph (normS overlaps cand+topk) -----------------
extern "C" void kernel_launch(void* const* d_in, const int* in_sizes, int n_in,
                              void* d_out, int out_size) {
    const float* student = (const float*)d_in[0];
    const float* teacher = (const float*)d_in[1];
    const int*   anchors = (const int*)d_in[2];
    float* out = (float*)d_out;

    static bool inited = false;
    static cudaStream_t s2;
    static cudaEvent_t evA, evB;
    if (!inited) {                       // first call is the uncaptured correctness run
        cudaStreamCreateWithFlags(&s2, cudaStreamNonBlocking);
        cudaEventCreateWithFlags(&evA, cudaEventDisableTiming);
        cudaEventCreateWithFlags(&evB, cudaEventDisableTiming);
        inited = true;
    }

    const int bpt = BB * HW / PIX;                   // 4608

    // stream 0: teacher norm + candidate Morton sort
    k_norm_t<<<bpt + 1, 256>>>(teacher, anchors);

    // fork: student norm on side stream (independent of teacher path)
    cudaEventRecord(evA, 0);
    cudaStreamWaitEvent(s2, evA, 0);
    k_norm_s<<<bpt, 256, 0, s2>>>(student);
    cudaEventRecord(evB, s2);

    // stream 0 continues: candidate sims + entropy, then top-k (overlaps normS)
    k_cand<<<BB * CAND / 8, 256>>>(anchors);
    k_topk<<<BB, 256>>>(anchors);

    // join: k_kl needs both g_sel (stream 0) and g_sn (side stream)
    cudaStreamWaitEvent(0, evB, 0);
    k_kl<<<BB * ANCH / 2, 64>>>(anchors, out);       // fused finalize writes out
}

// round 16
// speedup vs baseline: 1.1665x; 1.1665x over previous
#include <cuda_runtime.h>
#include <cuda_fp16.h>
#include <math.h>

#define BB 16
#define CC 384
#define HH 96
#define WW 96
#define HW (HH*WW)
#define CAND 2048
#define ANCH 512
#define KK2 49
#define TAU_INV 10.0f

// ---------------- scratch (device globals; no allocation anywhere) ----------------
__device__ __half g_tn[(size_t)BB*HW*CC];     // teacher, normalized, channels-last, fp16
__device__ __half g_sn[(size_t)BB*HW*CC];     // student,  normalized, channels-last, fp16
__device__ float g_sims[(size_t)BB*CAND*KK2]; // teacher sims (already /TAU), by ORIGINAL id
__device__ float g_ent[BB*CAND];              // by ORIGINAL id
__device__ int   g_order[CAND];               // candidate ids, Morton-sorted
__device__ int   g_sel[BB*ANCH];              // selected ids, Morton-binned per batch
__device__ float g_loss;

// pixel offsets dy*WW+dx, row-major 7x7, padded to 52 with 0 (center: L1-resident)
__constant__ int c_doff[52] = {
 -291,-290,-289,-288,-287,-286,-285,
 -195,-194,-193,-192,-191,-190,-189,
  -99, -98, -97, -96, -95, -94, -93,
   -3,  -2,  -1,   0,   1,   2,   3,
   93,  94,  95,  96,  97,  98,  99,
  189, 190, 191, 192, 193, 194, 195,
  285, 286, 287, 288, 289, 290, 291,
    0,   0,   0 };

__device__ __forceinline__ unsigned morton7(int y, int x) {
    unsigned m = 0;
#pragma unroll
    for (int i = 0; i < 7; i++)
        m |= (((unsigned)(y >> i) & 1u) << (2 * i + 1)) | (((unsigned)(x >> i) & 1u) << (2 * i));
    return m;
}

// order-preserving float -> unsigned key
__device__ __forceinline__ unsigned fkey(float v) {
    unsigned b = __float_as_uint(v);
    return b ^ (((int)b >> 31) | 0x80000000u);
}

// ---------------- candidate Morton sort body (256 threads, 4 pairs/round) ---------
__device__ void sort_candidates(const int* __restrict__ anchors,
                                unsigned* key, int* id) {
    int t = threadIdx.x;                 // 256
    if (t == 0) g_loss = 0.0f;
#pragma unroll
    for (int h = 0; h < 8; h++) {
        int m = t + h * 256;
        key[m] = morton7(anchors[2 * m], anchors[2 * m + 1]);
        id[m]  = m;
    }
    __syncthreads();
    for (int kk = 2; kk <= CAND; kk <<= 1) {
        for (int j = kk >> 1; j > 0; j >>= 1) {
            int ii[4], pp[4]; unsigned av[4], bv[4]; int ai[4], bi[4];
#pragma unroll
            for (int q = 0; q < 4; q++) {
                int tt = t + q * 256;
                ii[q] = ((tt & ~(j - 1)) << 1) | (tt & (j - 1));
                pp[q] = ii[q] | j;
                av[q] = key[ii[q]]; bv[q] = key[pp[q]];
                ai[q] = id[ii[q]];  bi[q] = id[pp[q]];
            }
#pragma unroll
            for (int q = 0; q < 4; q++) {
                bool up = ((ii[q] & kk) == 0);
                if ((av[q] > bv[q]) == up) {
                    key[ii[q]] = bv[q]; key[pp[q]] = av[q];
                    id[ii[q]]  = bi[q]; id[pp[q]]  = ai[q];
                }
            }
            __syncthreads();
        }
    }
#pragma unroll
    for (int h = 0; h < 8; h++) g_order[t + h * 256] = id[t + h * 256];
}

// ---------------- k1: fused L2-normalize + transpose + fp16 cast (+ sort block) ---
#define PIX 32
#define TROW 42   // halves per tile row (84B stride: 4B-aligned, <=2-way LDS conflicts)
__global__ void __launch_bounds__(256) k_norm_transpose(const float* __restrict__ teacher,
                                                        const float* __restrict__ student,
                                                        const int* __restrict__ anchors) {
    __shared__ __align__(16) __half tile[CC * TROW];   // 32256 B
    __shared__ float ssum[32][PIX + 1];                // 4224 B
    __shared__ float rinv[PIX];
    const int bpt = BB * HW / PIX;                     // 4608
    int blk  = blockIdx.x;
    if (blk >= 2 * bpt) {                              // sort block
        unsigned* key = (unsigned*)tile;
        int* id = (int*)(key + CAND);
        sort_candidates(anchors, key, id);
        return;
    }
    bool is_student = (blk >= bpt);
    if (is_student) blk -= bpt;
    const float* in = is_student ? student : teacher;
    __half* gout    = is_student ? g_sn : g_tn;

    int b    = blk / (HW / PIX);
    int pix0 = (blk % (HW / PIX)) * PIX;
    int t    = threadIdx.x;
    int p4   = t & 7;                        // float4 pixel index (0..7)
    int cr   = t >> 3;                       // channel row group (0..31)
    const float* src = in + (size_t)b * CC * HW + pix0;
    float a0 = 0.f, a1 = 0.f, a2 = 0.f, a3 = 0.f;
#pragma unroll
    for (int i = 0; i < CC / 32; i++) {      // 12 iters, LDG.128, fully coalesced
        int c = i * 32 + cr;
        float4 v = *(const float4*)(src + (size_t)c * HW + p4 * 4);
        *(__half2*)&tile[c * TROW + p4 * 4]     = __floats2half2_rn(v.x, v.y);
        *(__half2*)&tile[c * TROW + p4 * 4 + 2] = __floats2half2_rn(v.z, v.w);
        a0 = fmaf(v.x, v.x, a0);
        a1 = fmaf(v.y, v.y, a1);
        a2 = fmaf(v.z, v.z, a2);
        a3 = fmaf(v.w, v.w, a3);
    }
    ssum[cr][p4 * 4 + 0] = a0;
    ssum[cr][p4 * 4 + 1] = a1;
    ssum[cr][p4 * 4 + 2] = a2;
    ssum[cr][p4 * 4 + 3] = a3;
    __syncthreads();
    if (t < PIX) {                           // one warp: reduce 32 partials/pixel
        float s = 0.0f;
#pragma unroll
        for (int r = 0; r < 32; r++) s += ssum[r][t];
        rinv[t] = 1.0f / fmaxf(sqrtf(s), 1e-12f);
    }
    __syncthreads();
    int lane = t & 31, w = t >> 5;           // 8 warps, 4 pixels each
    __half2* dst = (__half2*)(gout + ((size_t)b * HW + pix0) * CC);
#pragma unroll
    for (int j = 0; j < PIX / 8; j++) {      // 4 pixels per warp
        int pp = w * (PIX / 8) + j;
        float r = rinv[pp];
#pragma unroll
        for (int i2 = 0; i2 < CC / 64; i2++) {  // 6, 128B coalesced half2 stores
            int h2i = lane + 32 * i2;            // half2 index 0..191
            int c = 2 * h2i;
            float va = __half2float(tile[c * TROW + pp]);
            float vb = __half2float(tile[(c + 1) * TROW + pp]);
            dst[(size_t)pp * (CC / 2) + h2i] = __floats2half2_rn(va * r, vb * r);
        }
    }
}

// ---------------- distributed window sims (fp16, fp32 accumulate) ----------------
template <int NB>
__device__ __forceinline__ void sims_batch(const uint4* __restrict__ cp, int ci,
                                           __half2 c0, __half2 c1, __half2 c2, __half2 c3,
                                           int obase, int g, float* s) {
    uint4 n[NB];
#pragma unroll
    for (int j = 0; j < NB; j++)
        n[j] = cp[ci + c_doff[g * 13 + obase + j] * (CC / 8)];
#pragma unroll
    for (int j = 0; j < NB; j++) {
        __half2 a = __hmul2(c0, *(__half2*)&n[j].x);
        a = __hfma2(c1, *(__half2*)&n[j].y, a);
        a = __hfma2(c2, *(__half2*)&n[j].z, a);
        a = __hfma2(c3, *(__half2*)&n[j].w, a);
        float2 f = __half22float2(a);
        s[obase + j] += f.x + f.y;
    }
}

__device__ __forceinline__ void window_sims13(const __half* __restrict__ feat,
                                              int b, int y, int x,
                                              int g, int l, float s[13]) {
    const uint4* cp = ((const uint4*)(feat + (size_t)b * HW * CC))
                    + (size_t)(y * WW + x) * (CC / 8);
#pragma unroll
    for (int j = 0; j < 13; j++) s[j] = 0.0f;
#pragma unroll
    for (int i = 0; i < 6; i++) {
        int ci = l + 8 * i;
        uint4 cv = cp[ci];
        __half2 c0 = *(__half2*)&cv.x, c1 = *(__half2*)&cv.y;
        __half2 c2 = *(__half2*)&cv.z, c3 = *(__half2*)&cv.w;
        sims_batch<5>(cp, ci, c0, c1, c2, c3, 0, g, s);
        sims_batch<4>(cp, ci, c0, c1, c2, c3, 5, g, s);
        sims_batch<4>(cp, ci, c0, c1, c2, c3, 9, g, s);
    }
#pragma unroll
    for (int j = 0; j < 13; j++) {
        float v = s[j];
        v += __shfl_xor_sync(0xffffffffu, v, 1);
        v += __shfl_xor_sync(0xffffffffu, v, 2);
        v += __shfl_xor_sync(0xffffffffu, v, 4);
        s[j] = v * TAU_INV;
    }
}

// ---------------- k2: candidate sims (stored) + entropy, Morton-ordered ----------
__global__ void __launch_bounds__(256, 4) k_cand(const int* __restrict__ anchors) {
    int gw   = (blockIdx.x * blockDim.x + threadIdx.x) >> 5;
    int lane = threadIdx.x & 31;
    if (gw >= BB * CAND) return;
    int b = gw >> 11;                  // / CAND
    int m = g_order[gw & (CAND - 1)];  // Morton-sorted processing order
    int y = anchors[2 * m], x = anchors[2 * m + 1];
    int g = lane >> 3, l = lane & 7;
    bool lead = (l == 0);

    float s[13];
    window_sims13(g_tn, b, y, x, g, l, s);

    float* srow = g_sims + ((size_t)(b << 11) + m) * KK2;
    if (lead) {
#pragma unroll
        for (int j = 0; j < 13; j++) {
            int o = g * 13 + j;
            if (o < KK2) srow[o] = s[j];
        }
    }

    float mx = -1e30f;
#pragma unroll
    for (int j = 0; j < 13; j++) {
        int o = g * 13 + j;
        if (o < KK2) mx = fmaxf(mx, s[j]);
    }
#pragma unroll
    for (int off = 16; off; off >>= 1) mx = fmaxf(mx, __shfl_xor_sync(0xffffffffu, mx, off));

    float S = 0.0f;
#pragma unroll
    for (int j = 0; j < 13; j++) {
        int o = g * 13 + j;
        if (lead && o < KK2) S += __expf(s[j] - mx);
    }
#pragma unroll
    for (int off = 16; off; off >>= 1) S += __shfl_xor_sync(0xffffffffu, S, off);
    float rS = 1.0f / S;

    float tacc = 0.0f;
#pragma unroll
    for (int j = 0; j < 13; j++) {
        int o = g * 13 + j;
        if (lead && o < KK2) {
            float p = __expf(s[j] - mx) * rS;
            tacc += p * __logf(p + 1e-6f);
        }
    }
#pragma unroll
    for (int off = 16; off; off >>= 1) tacc += __shfl_xor_sync(0xffffffffu, tacc, off);

    if (lane == 0) g_ent[(b << 11) | m] = -tacc;
}

// ---------------- k3: radix-select 512 smallest + Morton counting-sort -----------
// One block per batch, 256 threads. O(n) passes, ~18 barriers total (vs 111
// bitonic rounds). Output order = Morton-binned (8x8-pixel cells) for locality.
__global__ void __launch_bounds__(256) k_topk(const int* __restrict__ anchors) {
    __shared__ unsigned keys[CAND];          // 8 KB
    __shared__ unsigned hist[256];
    __shared__ int      sel[ANCH];
    __shared__ unsigned sh_prefix, sh_k, cnt_lo, cnt_eq;
    int b = blockIdx.x;
    int t = threadIdx.x;                     // 256
    int lane = t & 31;

#pragma unroll
    for (int h = 0; h < 8; h++) {
        int m = t + h * 256;
        keys[m] = fkey(g_ent[b * CAND + m]);
    }
    if (t == 0) { sh_prefix = 0u; sh_k = ANCH; cnt_lo = 0u; cnt_eq = 0u; }
    __syncthreads();

    // 4 x 8-bit radix passes to find the rank-512 threshold key
#pragma unroll
    for (int pass = 0; pass < 4; pass++) {
        int shift = 24 - pass * 8;
        unsigned prefix = sh_prefix, k = sh_k;
        unsigned mask_hi = (pass == 0) ? 0u : (0xFFFFFFFFu << (shift + 8));
        hist[t] = 0u;
        __syncthreads();
#pragma unroll
        for (int h = 0; h < 8; h++) {
            unsigned key = keys[t + h * 256];
            if ((key & mask_hi) == prefix)
                atomicAdd(&hist[(key >> shift) & 255], 1u);
        }
        __syncthreads();
        if (t < 32) {                        // one warp scans 256 bins
            unsigned l[8]; unsigned sum = 0;
#pragma unroll
            for (int j = 0; j < 8; j++) { l[j] = hist[t * 8 + j]; sum += l[j]; }
            unsigned inc = sum;
#pragma unroll
            for (int off = 1; off < 32; off <<= 1) {
                unsigned v = __shfl_up_sync(0xffffffffu, inc, off);
                if (lane >= off) inc += v;
            }
            unsigned excl = inc - sum;
            if (k > excl && k <= inc) {      // exactly one lane holds the crossing
                unsigned c = excl;
#pragma unroll
                for (int j = 0; j < 8; j++) {
                    if (k <= c + l[j]) { sh_prefix = prefix | ((unsigned)(t * 8 + j) << shift); sh_k = k - c; break; }
                    c += l[j];
                }
            }
        }
        __syncthreads();
    }

    unsigned T = sh_prefix;                  // exact rank-512 key
    unsigned need_eq = sh_k;                 // how many ==T to take
    unsigned below = ANCH - need_eq;         // count strictly < T

    // collect selected ids (order within groups irrelevant)
#pragma unroll
    for (int h = 0; h < 8; h++) {
        int m = t + h * 256;
        unsigned key = keys[m];
        if (key < T) {
            sel[atomicAdd(&cnt_lo, 1u)] = m;
        } else if (key == T) {
            unsigned e = atomicAdd(&cnt_eq, 1u);
            if (e < need_eq) sel[below + e] = m;
        }
    }
    __syncthreads();

    // counting-sort the 512 ids by top-8 Morton bits (8x8-pixel cells)
    hist[t] = 0u;
    __syncthreads();
#pragma unroll
    for (int h = 0; h < 2; h++) {
        int id = sel[t + h * 256];
        unsigned mk = morton7(anchors[2 * id], anchors[2 * id + 1]) >> 6;
        atomicAdd(&hist[mk], 1u);
    }
    __syncthreads();
    if (t < 32) {                            // exclusive offsets per bin
        unsigned l[8]; unsigned sum = 0;
#pragma unroll
        for (int j = 0; j < 8; j++) { l[j] = hist[t * 8 + j]; sum += l[j]; }
        unsigned inc = sum;
#pragma unroll
        for (int off = 1; off < 32; off <<= 1) {
            unsigned v = __shfl_up_sync(0xffffffffu, inc, off);
            if (lane >= off) inc += v;
        }
        unsigned c = inc - sum;
#pragma unroll
        for (int j = 0; j < 8; j++) { hist[t * 8 + j] = c; c += l[j]; }
    }
    __syncthreads();
#pragma unroll
    for (int h = 0; h < 2; h++) {
        int id = sel[t + h * 256];
        unsigned mk = morton7(anchors[2 * id], anchors[2 * id + 1]) >> 6;
        g_sel[b * ANCH + atomicAdd(&hist[mk], 1u)] = id;
    }
}

// ---------------- k4: KL divergence over selected anchors (Morton-binned) --------
__global__ void __launch_bounds__(256, 4) k_kl(const int* __restrict__ anchors) {
    int gw   = (blockIdx.x * blockDim.x + threadIdx.x) >> 5;
    int lane = threadIdx.x & 31;
    if (gw >= BB * ANCH) return;
    int b = gw >> 9;             // / ANCH
    int m = g_sel[gw];
    int y = anchors[2 * m], x = anchors[2 * m + 1];
    int g = lane >> 3, l = lane & 7;
    bool lead = (l == 0);

    float ss[13];
    window_sims13(g_sn, b, y, x, g, l, ss);

    const float* trow = g_sims + ((size_t)(b << 11) + m) * KK2;
    float st[13];
#pragma unroll
    for (int j = 0; j < 13; j++) {
        int o = g * 13 + j;
        st[j] = (o < KK2) ? trow[o] : -1e30f;   // group-broadcast loads
    }

    float mxs = -1e30f, mxt = -1e30f;
#pragma unroll
    for (int j = 0; j < 13; j++) {
        int o = g * 13 + j;
        if (o < KK2) mxs = fmaxf(mxs, ss[j]);
        mxt = fmaxf(mxt, st[j]);                // invalid slots are -1e30
    }
#pragma unroll
    for (int off = 16; off; off >>= 1) {
        mxs = fmaxf(mxs, __shfl_xor_sync(0xffffffffu, mxs, off));
        mxt = fmaxf(mxt, __shfl_xor_sync(0xffffffffu, mxt, off));
    }

    float Ss = 0.0f, St = 0.0f;
#pragma unroll
    for (int j = 0; j < 13; j++) {
        int o = g * 13 + j;
        if (lead && o < KK2) {
            Ss += __expf(ss[j] - mxs);
            St += __expf(st[j] - mxt);
        }
    }
#pragma unroll
    for (int off = 16; off; off >>= 1) {
        Ss += __shfl_xor_sync(0xffffffffu, Ss, off);
        St += __shfl_xor_sync(0xffffffffu, St, off);
    }
    float ls = __logf(Ss), lt = __logf(St);
    float rSt = 1.0f / St;

    float kacc = 0.0f;
#pragma unroll
    for (int j = 0; j < 13; j++) {
        int o = g * 13 + j;
        if (lead && o < KK2) {
            float dt = st[j] - mxt - lt;
            float ds = ss[j] - mxs - ls;
            kacc += __expf(st[j] - mxt) * (dt - ds);
        }
    }
#pragma unroll
    for (int off = 16; off; off >>= 1) kacc += __shfl_xor_sync(0xffffffffu, kacc, off);

    if (lane == 0) atomicAdd(&g_loss, kacc * rSt);
}

// ---------------- k5: finalize ----------------
__global__ void k_final(float* __restrict__ out) {
    out[0] = g_loss / (float)(BB * ANCH);
}

// ---------------- launch: kernel launches ONLY (graph-capture safe) ----------------
extern "C" void kernel_launch(void* const* d_in, const int* in_sizes, int n_in,
                              void* d_out, int out_size) {
    const float* student = (const float*)d_in[0];
    const float* teacher = (const float*)d_in[1];
    const int*   anchors = (const int*)d_in[2];
    float* out = (float*)d_out;

    int nt_blocks = 2 * BB * HW / PIX + 1;          // 9217: both tensors + sort block
    k_norm_transpose<<<nt_blocks, 256>>>(teacher, student, anchors);

    int cand_blocks = BB * CAND / 8;                // 4096 blocks, 8 warps each
    k_cand<<<cand_blocks, 256>>>(anchors);

    k_topk<<<BB, 256>>>(anchors);

    int kl_blocks = BB * ANCH / 8;                  // 1024 blocks
    k_kl<<<kl_blocks, 256>>>(anchors);

    k_final<<<1, 1>>>(out);
}

// round 17
// speedup vs baseline: 1.2789x; 1.0964x over previous
#include <cuda_runtime.h>
#include <cuda_fp16.h>
#include <math.h>

#define BB 16
#define CC 384
#define HH 96
#define WW 96
#define HW (HH*WW)
#define CAND 2048
#define ANCH 512
#define KK2 49
#define TAU_INV 10.0f

// ---------------- scratch (device globals; no allocation anywhere) ----------------
__device__ __half g_tn[(size_t)BB*HW*CC];     // teacher, normalized, channels-last, fp16
__device__ __half g_sn[(size_t)BB*HW*CC];     // student,  normalized, channels-last, fp16
__device__ float g_sims[(size_t)BB*CAND*KK2]; // teacher sims (already /TAU), by ORIGINAL id
__device__ float g_ent[BB*CAND];              // by ORIGINAL id
__device__ int   g_order[CAND];               // candidate ids, Morton-sorted
__device__ int   g_sel[BB*ANCH];              // selected ids, Morton-binned per batch
__device__ float g_loss;

// pixel offsets dy*WW+dx, row-major 7x7, padded to 52 with 0 (center: L1-resident)
__constant__ int c_doff[52] = {
 -291,-290,-289,-288,-287,-286,-285,
 -195,-194,-193,-192,-191,-190,-189,
  -99, -98, -97, -96, -95, -94, -93,
   -3,  -2,  -1,   0,   1,   2,   3,
   93,  94,  95,  96,  97,  98,  99,
  189, 190, 191, 192, 193, 194, 195,
  285, 286, 287, 288, 289, 290, 291,
    0,   0,   0 };

__device__ __forceinline__ unsigned morton7(int y, int x) {
    unsigned m = 0;
#pragma unroll
    for (int i = 0; i < 7; i++)
        m |= (((unsigned)(y >> i) & 1u) << (2 * i + 1)) | (((unsigned)(x >> i) & 1u) << (2 * i));
    return m;
}

// order-preserving float -> unsigned key
__device__ __forceinline__ unsigned fkey(float v) {
    unsigned b = __float_as_uint(v);
    return b ^ (((int)b >> 31) | 0x80000000u);
}

// ---------------- candidate Morton sort body (256 threads, 4 pairs/round) ---------
__device__ void sort_candidates(const int* __restrict__ anchors,
                                unsigned* key, int* id) {
    int t = threadIdx.x;                 // 256
    if (t == 0) g_loss = 0.0f;
#pragma unroll
    for (int h = 0; h < 8; h++) {
        int m = t + h * 256;
        key[m] = morton7(anchors[2 * m], anchors[2 * m + 1]);
        id[m]  = m;
    }
    __syncthreads();
    for (int kk = 2; kk <= CAND; kk <<= 1) {
        for (int j = kk >> 1; j > 0; j >>= 1) {
            int ii[4], pp[4]; unsigned av[4], bv[4]; int ai[4], bi[4];
#pragma unroll
            for (int q = 0; q < 4; q++) {
                int tt = t + q * 256;
                ii[q] = ((tt & ~(j - 1)) << 1) | (tt & (j - 1));
                pp[q] = ii[q] | j;
                av[q] = key[ii[q]]; bv[q] = key[pp[q]];
                ai[q] = id[ii[q]];  bi[q] = id[pp[q]];
            }
#pragma unroll
            for (int q = 0; q < 4; q++) {
                bool up = ((ii[q] & kk) == 0);
                if ((av[q] > bv[q]) == up) {
                    key[ii[q]] = bv[q]; key[pp[q]] = av[q];
                    id[ii[q]]  = bi[q]; id[pp[q]]  = ai[q];
                }
            }
            __syncthreads();
        }
    }
#pragma unroll
    for (int h = 0; h < 8; h++) g_order[t + h * 256] = id[t + h * 256];
}

// ---------------- shared norm-transpose body (fp16 tile) --------------------------
#define PIX 32
#define TROW 42   // halves per tile row (84B stride: 4B-aligned, <=2-way LDS conflicts)
__device__ __forceinline__ void norm_body(const float* __restrict__ in, __half* gout,
                                          int blk, __half* tile,
                                          float (*ssum)[PIX + 1], float* rinv) {
    int b    = blk / (HW / PIX);
    int pix0 = (blk % (HW / PIX)) * PIX;
    int t    = threadIdx.x;
    int p4   = t & 7;                        // float4 pixel index (0..7)
    int cr   = t >> 3;                       // channel row group (0..31)
    const float* src = in + (size_t)b * CC * HW + pix0;
    float a0 = 0.f, a1 = 0.f, a2 = 0.f, a3 = 0.f;
#pragma unroll
    for (int i = 0; i < CC / 32; i++) {      // 12 iters, LDG.128, fully coalesced
        int c = i * 32 + cr;
        float4 v = *(const float4*)(src + (size_t)c * HW + p4 * 4);
        *(__half2*)&tile[c * TROW + p4 * 4]     = __floats2half2_rn(v.x, v.y);
        *(__half2*)&tile[c * TROW + p4 * 4 + 2] = __floats2half2_rn(v.z, v.w);
        a0 = fmaf(v.x, v.x, a0);
        a1 = fmaf(v.y, v.y, a1);
        a2 = fmaf(v.z, v.z, a2);
        a3 = fmaf(v.w, v.w, a3);
    }
    ssum[cr][p4 * 4 + 0] = a0;
    ssum[cr][p4 * 4 + 1] = a1;
    ssum[cr][p4 * 4 + 2] = a2;
    ssum[cr][p4 * 4 + 3] = a3;
    __syncthreads();
    if (t < PIX) {                           // one warp: reduce 32 partials/pixel
        float s = 0.0f;
#pragma unroll
        for (int r = 0; r < 32; r++) s += ssum[r][t];
        rinv[t] = 1.0f / fmaxf(sqrtf(s), 1e-12f);
    }
    __syncthreads();
    int lane = t & 31, w = t >> 5;           // 8 warps, 4 pixels each
    __half2* dst = (__half2*)(gout + ((size_t)b * HW + pix0) * CC);
#pragma unroll
    for (int j = 0; j < PIX / 8; j++) {      // 4 pixels per warp
        int pp = w * (PIX / 8) + j;
        float r = rinv[pp];
#pragma unroll
        for (int i2 = 0; i2 < CC / 64; i2++) {  // 6, 128B coalesced half2 stores
            int h2i = lane + 32 * i2;            // half2 index 0..191
            int c = 2 * h2i;
            float va = __half2float(tile[c * TROW + pp]);
            float vb = __half2float(tile[(c + 1) * TROW + pp]);
            dst[(size_t)pp * (CC / 2) + h2i] = __floats2half2_rn(va * r, vb * r);
        }
    }
}

// ---------------- k1: teacher norm + candidate Morton sort ------------------------
__global__ void __launch_bounds__(256) k_norm_t(const float* __restrict__ teacher,
                                                const int* __restrict__ anchors) {
    __shared__ __align__(16) __half tile[CC * TROW];   // 32256 B
    __shared__ float ssum[32][PIX + 1];
    __shared__ float rinv[PIX];
    const int bpt = BB * HW / PIX;                     // 4608
    int blk = blockIdx.x;
    if (blk >= bpt) {                                  // sort block
        unsigned* key = (unsigned*)tile;
        int* id = (int*)(key + CAND);
        sort_candidates(anchors, key, id);
        return;
    }
    norm_body(teacher, g_tn, blk, tile, ssum, rinv);
}

// ---------------- distributed window sims (fp16, fp32 accumulate) ----------------
template <int NB>
__device__ __forceinline__ void sims_batch(const uint4* __restrict__ cp, int ci,
                                           __half2 c0, __half2 c1, __half2 c2, __half2 c3,
                                           int obase, int g, float* s) {
    uint4 n[NB];
#pragma unroll
    for (int j = 0; j < NB; j++)
        n[j] = cp[ci + c_doff[g * 13 + obase + j] * (CC / 8)];
#pragma unroll
    for (int j = 0; j < NB; j++) {
        __half2 a = __hmul2(c0, *(__half2*)&n[j].x);
        a = __hfma2(c1, *(__half2*)&n[j].y, a);
        a = __hfma2(c2, *(__half2*)&n[j].z, a);
        a = __hfma2(c3, *(__half2*)&n[j].w, a);
        float2 f = __half22float2(a);
        s[obase + j] += f.x + f.y;
    }
}

__device__ __forceinline__ void window_sims13(const __half* __restrict__ feat,
                                              int b, int y, int x,
                                              int g, int l, float s[13]) {
    const uint4* cp = ((const uint4*)(feat + (size_t)b * HW * CC))
                    + (size_t)(y * WW + x) * (CC / 8);
#pragma unroll
    for (int j = 0; j < 13; j++) s[j] = 0.0f;
#pragma unroll
    for (int i = 0; i < 6; i++) {
        int ci = l + 8 * i;
        uint4 cv = cp[ci];
        __half2 c0 = *(__half2*)&cv.x, c1 = *(__half2*)&cv.y;
        __half2 c2 = *(__half2*)&cv.z, c3 = *(__half2*)&cv.w;
        sims_batch<5>(cp, ci, c0, c1, c2, c3, 0, g, s);
        sims_batch<4>(cp, ci, c0, c1, c2, c3, 5, g, s);
        sims_batch<4>(cp, ci, c0, c1, c2, c3, 9, g, s);
    }
#pragma unroll
    for (int j = 0; j < 13; j++) {
        float v = s[j];
        v += __shfl_xor_sync(0xffffffffu, v, 1);
        v += __shfl_xor_sync(0xffffffffu, v, 2);
        v += __shfl_xor_sync(0xffffffffu, v, 4);
        s[j] = v * TAU_INV;
    }
}

// ---------------- candidate sims + entropy body (warp-per-candidate) -------------
__device__ __forceinline__ void cand_body(const int* __restrict__ anchors, int cblk) {
    int gw   = cblk * 8 + (threadIdx.x >> 5);
    int lane = threadIdx.x & 31;
    int b = gw >> 11;                  // / CAND
    int m = g_order[gw & (CAND - 1)];  // Morton-sorted processing order
    int y = anchors[2 * m], x = anchors[2 * m + 1];
    int g = lane >> 3, l = lane & 7;
    bool lead = (l == 0);

    float s[13];
    window_sims13(g_tn, b, y, x, g, l, s);

    float* srow = g_sims + ((size_t)(b << 11) + m) * KK2;
    if (lead) {
#pragma unroll
        for (int j = 0; j < 13; j++) {
            int o = g * 13 + j;
            if (o < KK2) srow[o] = s[j];
        }
    }

    float mx = -1e30f;
#pragma unroll
    for (int j = 0; j < 13; j++) {
        int o = g * 13 + j;
        if (o < KK2) mx = fmaxf(mx, s[j]);
    }
#pragma unroll
    for (int off = 16; off; off >>= 1) mx = fmaxf(mx, __shfl_xor_sync(0xffffffffu, mx, off));

    float S = 0.0f;
#pragma unroll
    for (int j = 0; j < 13; j++) {
        int o = g * 13 + j;
        if (lead && o < KK2) S += __expf(s[j] - mx);
    }
#pragma unroll
    for (int off = 16; off; off >>= 1) S += __shfl_xor_sync(0xffffffffu, S, off);
    float rS = 1.0f / S;

    float tacc = 0.0f;
#pragma unroll
    for (int j = 0; j < 13; j++) {
        int o = g * 13 + j;
        if (lead && o < KK2) {
            float p = __expf(s[j] - mx) * rS;
            tacc += p * __logf(p + 1e-6f);
        }
    }
#pragma unroll
    for (int off = 16; off; off >>= 1) tacc += __shfl_xor_sync(0xffffffffu, tacc, off);

    if (lane == 0) g_ent[(b << 11) | m] = -tacc;
}

// ---------------- k2: FUSED candidate-sims + student-norm (block-level overlap) ---
// Grid 8704 = 4096 cand + 4608 normS blocks, parity-interleaved so both kinds
// co-reside on every SM: cand is latency-bound, normS is DRAM-bound.
__global__ void __launch_bounds__(256, 4) k_mid(const float* __restrict__ student,
                                                const int* __restrict__ anchors) {
    __shared__ __align__(16) __half tile[CC * TROW];   // used by norm path only
    __shared__ float ssum[32][PIX + 1];
    __shared__ float rinv[PIX];
    int blk = blockIdx.x;
    if (blk < 8192) {
        if (blk & 1) norm_body(student, g_sn, blk >> 1, tile, ssum, rinv);
        else         cand_body(anchors, blk >> 1);
    } else {
        norm_body(student, g_sn, 4096 + (blk - 8192), tile, ssum, rinv);
    }
}

// ---------------- k3: radix-select 512 smallest + Morton counting-sort -----------
__global__ void __launch_bounds__(256) k_topk(const int* __restrict__ anchors) {
    __shared__ unsigned keys[CAND];          // 8 KB
    __shared__ unsigned hist[256];
    __shared__ int      sel[ANCH];
    __shared__ unsigned sh_prefix, sh_k, cnt_lo, cnt_eq;
    int b = blockIdx.x;
    int t = threadIdx.x;                     // 256
    int lane = t & 31;

#pragma unroll
    for (int h = 0; h < 8; h++) {
        int m = t + h * 256;
        keys[m] = fkey(g_ent[b * CAND + m]);
    }
    if (t == 0) { sh_prefix = 0u; sh_k = ANCH; cnt_lo = 0u; cnt_eq = 0u; }
    __syncthreads();

#pragma unroll
    for (int pass = 0; pass < 4; pass++) {
        int shift = 24 - pass * 8;
        unsigned prefix = sh_prefix, k = sh_k;
        unsigned mask_hi = (pass == 0) ? 0u : (0xFFFFFFFFu << (shift + 8));
        hist[t] = 0u;
        __syncthreads();
#pragma unroll
        for (int h = 0; h < 8; h++) {
            unsigned key = keys[t + h * 256];
            if ((key & mask_hi) == prefix)
                atomicAdd(&hist[(key >> shift) & 255], 1u);
        }
        __syncthreads();
        if (t < 32) {                        // one warp scans 256 bins
            unsigned l[8]; unsigned sum = 0;
#pragma unroll
            for (int j = 0; j < 8; j++) { l[j] = hist[t * 8 + j]; sum += l[j]; }
            unsigned inc = sum;
#pragma unroll
            for (int off = 1; off < 32; off <<= 1) {
                unsigned v = __shfl_up_sync(0xffffffffu, inc, off);
                if (lane >= off) inc += v;
            }
            unsigned excl = inc - sum;
            if (k > excl && k <= inc) {
                unsigned c = excl;
#pragma unroll
                for (int j = 0; j < 8; j++) {
                    if (k <= c + l[j]) { sh_prefix = prefix | ((unsigned)(t * 8 + j) << shift); sh_k = k - c; break; }
                    c += l[j];
                }
            }
        }
        __syncthreads();
    }

    unsigned T = sh_prefix;
    unsigned need_eq = sh_k;
    unsigned below = ANCH - need_eq;

#pragma unroll
    for (int h = 0; h < 8; h++) {
        int m = t + h * 256;
        unsigned key = keys[m];
        if (key < T) {
            sel[atomicAdd(&cnt_lo, 1u)] = m;
        } else if (key == T) {
            unsigned e = atomicAdd(&cnt_eq, 1u);
            if (e < need_eq) sel[below + e] = m;
        }
    }
    __syncthreads();

    hist[t] = 0u;
    __syncthreads();
#pragma unroll
    for (int h = 0; h < 2; h++) {
        int id = sel[t + h * 256];
        unsigned mk = morton7(anchors[2 * id], anchors[2 * id + 1]) >> 6;
        atomicAdd(&hist[mk], 1u);
    }
    __syncthreads();
    if (t < 32) {
        unsigned l[8]; unsigned sum = 0;
#pragma unroll
        for (int j = 0; j < 8; j++) { l[j] = hist[t * 8 + j]; sum += l[j]; }
        unsigned inc = sum;
#pragma unroll
        for (int off = 1; off < 32; off <<= 1) {
            unsigned v = __shfl_up_sync(0xffffffffu, inc, off);
            if (lane >= off) inc += v;
        }
        unsigned c = inc - sum;
#pragma unroll
        for (int j = 0; j < 8; j++) { hist[t * 8 + j] = c; c += l[j]; }
    }
    __syncthreads();
#pragma unroll
    for (int h = 0; h < 2; h++) {
        int id = sel[t + h * 256];
        unsigned mk = morton7(anchors[2 * id], anchors[2 * id + 1]) >> 6;
        g_sel[b * ANCH + atomicAdd(&hist[mk], 1u)] = id;
    }
}

// ---------------- k4: KL divergence over selected anchors (Morton-binned) --------
__global__ void __launch_bounds__(256, 4) k_kl(const int* __restrict__ anchors) {
    int gw   = (blockIdx.x * blockDim.x + threadIdx.x) >> 5;
    int lane = threadIdx.x & 31;
    if (gw >= BB * ANCH) return;
    int b = gw >> 9;             // / ANCH
    int m = g_sel[gw];
    int y = anchors[2 * m], x = anchors[2 * m + 1];
    int g = lane >> 3, l = lane & 7;
    bool lead = (l == 0);

    float ss[13];
    window_sims13(g_sn, b, y, x, g, l, ss);

    const float* trow = g_sims + ((size_t)(b << 11) + m) * KK2;
    float st[13];
#pragma unroll
    for (int j = 0; j < 13; j++) {
        int o = g * 13 + j;
        st[j] = (o < KK2) ? trow[o] : -1e30f;   // group-broadcast loads
    }

    float mxs = -1e30f, mxt = -1e30f;
#pragma unroll
    for (int j = 0; j < 13; j++) {
        int o = g * 13 + j;
        if (o < KK2) mxs = fmaxf(mxs, ss[j]);
        mxt = fmaxf(mxt, st[j]);                // invalid slots are -1e30
    }
#pragma unroll
    for (int off = 16; off; off >>= 1) {
        mxs = fmaxf(mxs, __shfl_xor_sync(0xffffffffu, mxs, off));
        mxt = fmaxf(mxt, __shfl_xor_sync(0xffffffffu, mxt, off));
    }

    float Ss = 0.0f, St = 0.0f;
#pragma unroll
    for (int j = 0; j < 13; j++) {
        int o = g * 13 + j;
        if (lead && o < KK2) {
            Ss += __expf(ss[j] - mxs);
            St += __expf(st[j] - mxt);
        }
    }
#pragma unroll
    for (int off = 16; off; off >>= 1) {
        Ss += __shfl_xor_sync(0xffffffffu, Ss, off);
        St += __shfl_xor_sync(0xffffffffu, St, off);
    }
    float ls = __logf(Ss), lt = __logf(St);
    float rSt = 1.0f / St;

    float kacc = 0.0f;
#pragma unroll
    for (int j = 0; j < 13; j++) {
        int o = g * 13 + j;
        if (lead && o < KK2) {
            float dt = st[j] - mxt - lt;
            float ds = ss[j] - mxs - ls;
            kacc += __expf(st[j] - mxt) * (dt - ds);
        }
    }
#pragma unroll
    for (int off = 16; off; off >>= 1) kacc += __shfl_xor_sync(0xffffffffu, kacc, off);

    if (lane == 0) atomicAdd(&g_loss, kacc * rSt);
}

// ---------------- k5: finalize ----------------
__global__ void k_final(float* __restrict__ out) {
    out[0] = g_loss / (float)(BB * ANCH);
}

// ---------------- launch: kernel launches ONLY (graph-capture safe) ----------------
extern "C" void kernel_launch(void* const* d_in, const int* in_sizes, int n_in,
                              void* d_out, int out_size) {
    const float* student = (const float*)d_in[0];
    const float* teacher = (const float*)d_in[1];
    const int*   anchors = (const int*)d_in[2];
    float* out = (float*)d_out;

    const int bpt = BB * HW / PIX;                  // 4608

    k_norm_t<<<bpt + 1, 256>>>(teacher, anchors);   // teacher norm + Morton sort

    k_mid<<<4096 + bpt, 256>>>(student, anchors);   // cand sims + student norm, fused

    k_topk<<<BB, 256>>>(anchors);

    k_kl<<<BB * ANCH / 8, 256>>>(anchors);

    k_final<<<1, 1>>>(out);
}